// round 1
// baseline (speedup 1.0000x reference)
#include <cuda_runtime.h>
#include <math.h>

#define Bn  8
#define TQn 64
#define TKn 8192
#define Hn  256

// Scratch for transformed query qt[b,q,h] = sum_o query[b,q,o] * W[o,h]
__device__ float g_qt[Bn * TQn * Hn];

// ---------------------------------------------------------------------------
// Kernel 1: qt = Q @ W   (bias is dropped: constant per softmax row)
// Grid: 64 blocks, each handles 8 (b,q) rows x all 256 h columns.
// ---------------------------------------------------------------------------
__global__ void k_transform(const float* __restrict__ query,
                            const float* __restrict__ W) {
    __shared__ float qs[8][Hn];
    const int t  = threadIdx.x;            // 256 threads
    const int r0 = blockIdx.x * 8;         // first global (b*64+q) row

    #pragma unroll
    for (int i = 0; i < 8; ++i) {
        int idx = i * 256 + t;
        qs[idx >> 8][idx & 255] = query[(size_t)r0 * Hn + idx];
    }
    __syncthreads();

    float acc[8] = {0.f, 0.f, 0.f, 0.f, 0.f, 0.f, 0.f, 0.f};
    #pragma unroll 4
    for (int o = 0; o < Hn; ++o) {
        float wv = W[o * Hn + t];          // coalesced across threads
        #pragma unroll
        for (int r = 0; r < 8; ++r) acc[r] += qs[r][o] * wv;  // LDS broadcast
    }
    #pragma unroll
    for (int r = 0; r < 8; ++r)
        g_qt[(size_t)(r0 + r) * Hn + t] = acc[r];
}

// ---------------------------------------------------------------------------
// Kernel 2: scores[b,q,k] = sum_h qt[b,q,h] * keys[b,k,h]
// Per block: M=64 (all q), N=128 keys, K=256 in chunks of 32.
// k-major transposed smem tiles with +1 pad -> conflict-free fragment loads.
// Thread (ry,cx) = (t>>4, t&15) computes rows {ry+16i}, cols {cx+16j}.
// ---------------------------------------------------------------------------
__global__ void k_scores(const float* __restrict__ keys,
                         float* __restrict__ scr) {
    __shared__ float As[32][TQn + 1];      // [k][m]
    __shared__ float Bs[32][128 + 1];      // [k][n]

    const int b  = blockIdx.y;
    const int n0 = blockIdx.x * 128;
    const float* A  = g_qt + (size_t)b * TQn * Hn;
    const float* Bg = keys + ((size_t)b * TKn + n0) * Hn;

    const int t  = threadIdx.x;
    const int ry = t >> 4;                 // 0..15
    const int cx = t & 15;                 // 0..15

    float acc[4][8];
    #pragma unroll
    for (int i = 0; i < 4; ++i)
        #pragma unroll
        for (int j = 0; j < 8; ++j) acc[i][j] = 0.f;

    for (int k0 = 0; k0 < Hn; k0 += 32) {
        #pragma unroll
        for (int i = 0; i < 2; ++i) {       // A tile: 64x32 = 512 float4
            int idx = i * 256 + t;
            int m = idx >> 3, c4 = (idx & 7) * 4;
            float4 f = *(const float4*)(A + m * Hn + k0 + c4);
            As[c4 + 0][m] = f.x; As[c4 + 1][m] = f.y;
            As[c4 + 2][m] = f.z; As[c4 + 3][m] = f.w;
        }
        #pragma unroll
        for (int i = 0; i < 4; ++i) {       // B tile: 128x32 = 1024 float4
            int idx = i * 256 + t;
            int n = idx >> 3, c4 = (idx & 7) * 4;
            float4 f = *(const float4*)(Bg + n * Hn + k0 + c4);
            Bs[c4 + 0][n] = f.x; Bs[c4 + 1][n] = f.y;
            Bs[c4 + 2][n] = f.z; Bs[c4 + 3][n] = f.w;
        }
        __syncthreads();

        #pragma unroll 8
        for (int k = 0; k < 32; ++k) {
            float a[4], bb[8];
            #pragma unroll
            for (int i = 0; i < 4; ++i) a[i]  = As[k][ry + 16 * i];
            #pragma unroll
            for (int j = 0; j < 8; ++j) bb[j] = Bs[k][cx + 16 * j];
            #pragma unroll
            for (int i = 0; i < 4; ++i)
                #pragma unroll
                for (int j = 0; j < 8; ++j)
                    acc[i][j] += a[i] * bb[j];
        }
        __syncthreads();
    }

    #pragma unroll
    for (int i = 0; i < 4; ++i) {
        int m = ry + 16 * i;
        float* out = scr + ((size_t)b * TQn + m) * TKn + n0 + cx;
        #pragma unroll
        for (int j = 0; j < 8; ++j) out[16 * j] = acc[i][j];
    }
}

// ---------------------------------------------------------------------------
// Kernel 3: in-place row softmax over TK=8192. One block per (b,q) row.
// Row staged in smem: 1 gmem read + 1 gmem write.
// ---------------------------------------------------------------------------
__global__ void k_softmax(float* __restrict__ w) {
    __shared__ float buf[TKn];
    __shared__ float red[8];

    float4* row4 = (float4*)(w + (size_t)blockIdx.x * TKn);
    float4* b4   = (float4*)buf;
    const int t  = threadIdx.x;            // 256 threads, 8 float4 each

    float m = -3.4e38f;
    #pragma unroll
    for (int i = 0; i < 8; ++i) {
        float4 v = row4[i * 256 + t];
        b4[i * 256 + t] = v;
        m = fmaxf(m, fmaxf(fmaxf(v.x, v.y), fmaxf(v.z, v.w)));
    }
    #pragma unroll
    for (int o = 16; o; o >>= 1) m = fmaxf(m, __shfl_xor_sync(0xffffffffu, m, o));
    if ((t & 31) == 0) red[t >> 5] = m;
    __syncthreads();
    m = red[0];
    #pragma unroll
    for (int r = 1; r < 8; ++r) m = fmaxf(m, red[r]);

    float s = 0.f;
    #pragma unroll
    for (int i = 0; i < 8; ++i) {
        float4 v = b4[i * 256 + t];
        v.x = __expf(v.x - m); v.y = __expf(v.y - m);
        v.z = __expf(v.z - m); v.w = __expf(v.w - m);
        b4[i * 256 + t] = v;
        s += (v.x + v.y) + (v.z + v.w);
    }
    #pragma unroll
    for (int o = 16; o; o >>= 1) s += __shfl_xor_sync(0xffffffffu, s, o);
    __syncthreads();                       // all reads of red(max) done
    if ((t & 31) == 0) red[t >> 5] = s;
    __syncthreads();
    s = 0.f;
    #pragma unroll
    for (int r = 0; r < 8; ++r) s += red[r];
    const float inv = 1.f / s;

    #pragma unroll
    for (int i = 0; i < 8; ++i) {
        float4 v = b4[i * 256 + t];
        v.x *= inv; v.y *= inv; v.z *= inv; v.w *= inv;
        row4[i * 256 + t] = v;
    }
}

// ---------------------------------------------------------------------------
// Kernel 4: context[b,q,h] += sum_{k in chunk} weights[b,q,k] * keys[b,k,h]
// Split-K: 64 chunks of 128 keys per batch -> 512 blocks; atomicAdd epilogue.
// Thread (ry,cx) = (t>>5, t&31): rows {ry+8i}, cols {cx+32j} (8x8 microtile).
// ---------------------------------------------------------------------------
__global__ void k_context(const float* __restrict__ keys,
                          const float* __restrict__ wts,
                          float* __restrict__ ctx) {
    __shared__ float Wst[32][TQn + 1];     // [k][m], transposed, padded
    __shared__ float Kt[32][Hn];           // [k][h], natural layout

    const int b  = blockIdx.y;
    const int kb = blockIdx.x * 128;
    const int t  = threadIdx.x;
    const int ry = t >> 5;                 // 0..7 (warp id -> a-frag broadcast)
    const int cx = t & 31;                 // 0..31

    float acc[8][8];
    #pragma unroll
    for (int i = 0; i < 8; ++i)
        #pragma unroll
        for (int j = 0; j < 8; ++j) acc[i][j] = 0.f;

    for (int kt = 0; kt < 128; kt += 32) {
        #pragma unroll
        for (int i = 0; i < 2; ++i) {       // weights tile 64x32
            int idx = i * 256 + t;
            int m = idx >> 3, c4 = (idx & 7) * 4;
            float4 f = *(const float4*)(wts + ((size_t)b * TQn + m) * TKn + kb + kt + c4);
            Wst[c4 + 0][m] = f.x; Wst[c4 + 1][m] = f.y;
            Wst[c4 + 2][m] = f.z; Wst[c4 + 3][m] = f.w;
        }
        #pragma unroll
        for (int i = 0; i < 8; ++i) {       // keys tile 32x256
            int idx = i * 256 + t;
            int k = idx >> 6, h4 = (idx & 63) * 4;
            *(float4*)&Kt[k][h4] =
                *(const float4*)(keys + ((size_t)b * TKn + kb + kt + k) * Hn + h4);
        }
        __syncthreads();

        #pragma unroll 8
        for (int k = 0; k < 32; ++k) {
            float a[8], bb[8];
            #pragma unroll
            for (int i = 0; i < 8; ++i) a[i]  = Wst[k][ry + 8 * i];   // broadcast
            #pragma unroll
            for (int j = 0; j < 8; ++j) bb[j] = Kt[k][cx + 32 * j];   // conflict-free
            #pragma unroll
            for (int i = 0; i < 8; ++i)
                #pragma unroll
                for (int j = 0; j < 8; ++j)
                    acc[i][j] += a[i] * bb[j];
        }
        __syncthreads();
    }

    #pragma unroll
    for (int i = 0; i < 8; ++i) {
        int m = ry + 8 * i;
        float* out = ctx + ((size_t)b * TQn + m) * Hn + cx;
        #pragma unroll
        for (int j = 0; j < 8; ++j)
            atomicAdd(&out[32 * j], acc[i][j]);   // coalesced REDG per (i,j)
    }
}

// ---------------------------------------------------------------------------
// Launch: inputs per metadata order: query, keys, Wa_w, Wa_b (bias unused —
// constant per softmax row, cancels exactly). Output tuple order: context
// [B*TQ*H f32] then weights [B*TQ*TK f32]; weights region doubles as scores
// scratch before the in-place softmax.
// ---------------------------------------------------------------------------
extern "C" void kernel_launch(void* const* d_in, const int* in_sizes, int n_in,
                              void* d_out, int out_size) {
    const float* query = (const float*)d_in[0];
    const float* keys  = (const float*)d_in[1];
    const float* W     = (const float*)d_in[2];
    // d_in[3] (bias) intentionally unused.

    float* ctx = (float*)d_out;
    float* wts = ctx + (size_t)Bn * TQn * Hn;

    k_transform<<<(Bn * TQn) / 8, 256>>>(query, W);
    k_scores<<<dim3(TKn / 128, Bn), 256>>>(keys, wts);
    k_softmax<<<Bn * TQn, 256>>>(wts);
    cudaMemsetAsync(ctx, 0, (size_t)Bn * TQn * Hn * sizeof(float), 0);
    k_context<<<dim3(TKn / 128, Bn), 256>>>(keys, wts, ctx);
}

// round 2
// speedup vs baseline: 1.3815x; 1.3815x over previous
#include <cuda_runtime.h>
#include <cuda_bf16.h>
#include <math.h>
#include <stdint.h>

#define Bn  8
#define TQn 64
#define TKn 8192
#define Hn  256

// Scratch: qt[b,q,h] = sum_o query[b,q,o] * W[o,h]   (bias dropped: softmax-invariant)
__device__ float g_qt[Bn * TQn * Hn];

// ---------------------------------------------------------------------------
// MMA helpers (m16n8k16 bf16, f32 accum) + ldmatrix
// ---------------------------------------------------------------------------
__device__ __forceinline__ uint32_t sptr(const void* p) {
    return (uint32_t)__cvta_generic_to_shared(p);
}
__device__ __forceinline__ void ldsmx4(uint32_t* r, uint32_t a) {
    asm volatile("ldmatrix.sync.aligned.m8n8.x4.shared.b16 {%0,%1,%2,%3},[%4];"
        : "=r"(r[0]), "=r"(r[1]), "=r"(r[2]), "=r"(r[3]) : "r"(a));
}
__device__ __forceinline__ void ldsmx2(uint32_t* r, uint32_t a) {
    asm volatile("ldmatrix.sync.aligned.m8n8.x2.shared.b16 {%0,%1},[%2];"
        : "=r"(r[0]), "=r"(r[1]) : "r"(a));
}
__device__ __forceinline__ void ldsmx2t(uint32_t* r, uint32_t a) {
    asm volatile("ldmatrix.sync.aligned.m8n8.x2.trans.shared.b16 {%0,%1},[%2];"
        : "=r"(r[0]), "=r"(r[1]) : "r"(a));
}
__device__ __forceinline__ void mma16816(float* c, const uint32_t* a, const uint32_t* b) {
    asm volatile(
        "mma.sync.aligned.m16n8k16.row.col.f32.bf16.bf16.f32 "
        "{%0,%1,%2,%3},{%4,%5,%6,%7},{%8,%9},{%0,%1,%2,%3};"
        : "+f"(c[0]), "+f"(c[1]), "+f"(c[2]), "+f"(c[3])
        : "r"(a[0]), "r"(a[1]), "r"(a[2]), "r"(a[3]), "r"(b[0]), "r"(b[1]));
}
// fp32 -> bf16 hi + bf16 lo(residual). Pair error ~2^-24 relative.
__device__ __forceinline__ void split_store(float x, __nv_bfloat16* ph, __nv_bfloat16* pl) {
    __nv_bfloat16 h = __float2bfloat16(x);
    *ph = h;
    *pl = __float2bfloat16(x - __bfloat162float(h));
}

#define SLDA 40   // 32 + 8 pad: row stride 80B -> conflict-free ldmatrix
#define KLDA 264  // 256 + 8 pad: row stride 528B -> 16B-distinct mod 128

// ---------------------------------------------------------------------------
// Kernel 1: qt = Q @ W (fp32, tiny: 67 MFLOP)
// ---------------------------------------------------------------------------
__global__ void k_transform(const float* __restrict__ query,
                            const float* __restrict__ W) {
    __shared__ float qs[8][Hn];
    const int t  = threadIdx.x;
    const int r0 = blockIdx.x * 8;

    #pragma unroll
    for (int i = 0; i < 8; ++i) {
        int idx = i * 256 + t;
        qs[idx >> 8][idx & 255] = query[(size_t)r0 * Hn + idx];
    }
    __syncthreads();

    float acc[8] = {0.f, 0.f, 0.f, 0.f, 0.f, 0.f, 0.f, 0.f};
    #pragma unroll 4
    for (int o = 0; o < Hn; ++o) {
        float wv = W[o * Hn + t];
        #pragma unroll
        for (int r = 0; r < 8; ++r) acc[r] += qs[r][o] * wv;
    }
    #pragma unroll
    for (int r = 0; r < 8; ++r)
        g_qt[(size_t)(r0 + r) * Hn + t] = acc[r];
}

// ---------------------------------------------------------------------------
// Kernel 2: scores[b,q,k] = sum_h qt[b,q,h]*keys[b,k,h]  -- tensor cores.
// Block: M=64 (all q), N=128 keys, K=256 by 32. 8 warps = 2(M) x 4(N),
// warp tile 32x32. 3-term bf16 hi/lo split, f32 accumulate.
// ---------------------------------------------------------------------------
__global__ void __launch_bounds__(256)
k_scores(const float* __restrict__ keys, float* __restrict__ scr) {
    __shared__ __nv_bfloat16 Ah[64][SLDA],  Al[64][SLDA];
    __shared__ __nv_bfloat16 Bh[128][SLDA], Bl[128][SLDA];

    const int b  = blockIdx.y;
    const int n0 = blockIdx.x * 128;
    const float* A  = g_qt + (size_t)b * TQn * Hn;
    const float* Bg = keys + ((size_t)b * TKn + n0) * Hn;

    const int t = threadIdx.x, wid = t >> 5, lane = t & 31;
    const int wm = wid >> 2, wn = wid & 3;

    float c[2][4][4];
    #pragma unroll
    for (int i = 0; i < 2; ++i)
        #pragma unroll
        for (int j = 0; j < 4; ++j)
            #pragma unroll
            for (int v = 0; v < 4; ++v) c[i][j][v] = 0.f;

    // ldmatrix per-lane address components
    const int arow = wm * 32 + (lane & 15);
    const int acol = ((lane >> 4) & 1) * 8;
    const int brow = wn * 32 + (lane & 7);
    const int bcol = ((lane >> 3) & 1) * 8;

    for (int k0 = 0; k0 < Hn; k0 += 32) {
        #pragma unroll
        for (int i = 0; i < 2; ++i) {                  // A tile 64x32 fp32
            int idx = i * 256 + t;
            int m = idx >> 3, cc = (idx & 7) * 4;
            float4 f = *(const float4*)(A + m * Hn + k0 + cc);
            split_store(f.x, &Ah[m][cc + 0], &Al[m][cc + 0]);
            split_store(f.y, &Ah[m][cc + 1], &Al[m][cc + 1]);
            split_store(f.z, &Ah[m][cc + 2], &Al[m][cc + 2]);
            split_store(f.w, &Ah[m][cc + 3], &Al[m][cc + 3]);
        }
        #pragma unroll
        for (int i = 0; i < 4; ++i) {                  // B tile 128x32 fp32
            int idx = i * 256 + t;
            int n = idx >> 3, cc = (idx & 7) * 4;
            float4 f = *(const float4*)(Bg + (size_t)n * Hn + k0 + cc);
            split_store(f.x, &Bh[n][cc + 0], &Bl[n][cc + 0]);
            split_store(f.y, &Bh[n][cc + 1], &Bl[n][cc + 1]);
            split_store(f.z, &Bh[n][cc + 2], &Bl[n][cc + 2]);
            split_store(f.w, &Bh[n][cc + 3], &Bl[n][cc + 3]);
        }
        __syncthreads();

        #pragma unroll
        for (int ks = 0; ks < 2; ++ks) {
            const int kk = ks * 16;
            uint32_t ah[2][4], alr[2][4];
            #pragma unroll
            for (int i = 0; i < 2; ++i) {
                ldsmx4(ah[i],  sptr(&Ah[arow + i * 16][kk + acol]));
                ldsmx4(alr[i], sptr(&Al[arow + i * 16][kk + acol]));
            }
            uint32_t bh[4][2], blr[4][2];
            #pragma unroll
            for (int j = 0; j < 4; ++j) {
                ldsmx2(bh[j],  sptr(&Bh[brow + j * 8][kk + bcol]));
                ldsmx2(blr[j], sptr(&Bl[brow + j * 8][kk + bcol]));
            }
            #pragma unroll
            for (int i = 0; i < 2; ++i)
                #pragma unroll
                for (int j = 0; j < 4; ++j) {
                    mma16816(c[i][j], ah[i],  bh[j]);
                    mma16816(c[i][j], ah[i],  blr[j]);
                    mma16816(c[i][j], alr[i], bh[j]);
                }
        }
        __syncthreads();
    }

    #pragma unroll
    for (int i = 0; i < 2; ++i) {
        int row = wm * 32 + i * 16 + (lane >> 2);
        #pragma unroll
        for (int j = 0; j < 4; ++j) {
            int col = n0 + wn * 32 + j * 8 + (lane & 3) * 2;
            float* o = scr + ((size_t)b * TQn + row) * TKn + col;
            *(float2*)o              = make_float2(c[i][j][0], c[i][j][1]);
            *(float2*)(o + 8 * TKn)  = make_float2(c[i][j][2], c[i][j][3]);
        }
    }
}

// ---------------------------------------------------------------------------
// Kernel 3: in-place row softmax over TK=8192. 512 threads/row.
// ---------------------------------------------------------------------------
__global__ void __launch_bounds__(512) k_softmax(float* __restrict__ w) {
    __shared__ float buf[TKn];
    __shared__ float red[16];

    float4* row4 = (float4*)(w + (size_t)blockIdx.x * TKn);
    float4* b4   = (float4*)buf;
    const int t = threadIdx.x;

    float m = -3.4e38f;
    #pragma unroll
    for (int i = 0; i < 4; ++i) {
        float4 v = row4[i * 512 + t];
        b4[i * 512 + t] = v;
        m = fmaxf(m, fmaxf(fmaxf(v.x, v.y), fmaxf(v.z, v.w)));
    }
    #pragma unroll
    for (int o = 16; o; o >>= 1) m = fmaxf(m, __shfl_xor_sync(0xffffffffu, m, o));
    if ((t & 31) == 0) red[t >> 5] = m;
    __syncthreads();
    m = red[0];
    #pragma unroll
    for (int r = 1; r < 16; ++r) m = fmaxf(m, red[r]);

    float s = 0.f;
    #pragma unroll
    for (int i = 0; i < 4; ++i) {
        float4 v = b4[i * 512 + t];
        v.x = __expf(v.x - m); v.y = __expf(v.y - m);
        v.z = __expf(v.z - m); v.w = __expf(v.w - m);
        b4[i * 512 + t] = v;
        s += (v.x + v.y) + (v.z + v.w);
    }
    #pragma unroll
    for (int o = 16; o; o >>= 1) s += __shfl_xor_sync(0xffffffffu, s, o);
    __syncthreads();
    if ((t & 31) == 0) red[t >> 5] = s;
    __syncthreads();
    s = 0.f;
    #pragma unroll
    for (int r = 0; r < 16; ++r) s += red[r];
    const float inv = 1.f / s;

    #pragma unroll
    for (int i = 0; i < 4; ++i) {
        float4 v = b4[i * 512 + t];
        v.x *= inv; v.y *= inv; v.z *= inv; v.w *= inv;
        row4[i * 512 + t] = v;
    }
}

// ---------------------------------------------------------------------------
// Kernel 4: context[b,q,h] += sum_k weights[b,q,k]*keys[b,k,h] -- tensor cores.
// Block covers 256 keys (split-K over 32 blocks/batch), M=64 q, N=256 h.
// 16 warps = 2(M) x 8(N), warp tile 32x32. keys loaded [k][h]: B frag via
// ldmatrix.trans. f32 atomicAdd epilogue.
// ---------------------------------------------------------------------------
__global__ void __launch_bounds__(512)
k_context(const float* __restrict__ keys, const float* __restrict__ wts,
          float* __restrict__ ctx) {
    __shared__ __nv_bfloat16 Wh[64][SLDA], Wl[64][SLDA];
    __shared__ __nv_bfloat16 Kh[32][KLDA], Kl[32][KLDA];

    const int b  = blockIdx.y;
    const int kb = blockIdx.x * 256;
    const int t = threadIdx.x, wid = t >> 5, lane = t & 31;
    const int wm = wid >> 3, wn = wid & 7;

    float c[2][4][4];
    #pragma unroll
    for (int i = 0; i < 2; ++i)
        #pragma unroll
        for (int j = 0; j < 4; ++j)
            #pragma unroll
            for (int v = 0; v < 4; ++v) c[i][j][v] = 0.f;

    const int arow = wm * 32 + (lane & 15);
    const int acol = ((lane >> 4) & 1) * 8;
    const int krow = (lane & 15);              // trans ldmatrix: rows are k

    for (int kt = 0; kt < 256; kt += 32) {
        {                                       // W tile 64x32 fp32 (1 f4/thr)
            int m = t >> 3, cc = (t & 7) * 4;
            float4 f = *(const float4*)(wts + ((size_t)b * TQn + m) * TKn + kb + kt + cc);
            split_store(f.x, &Wh[m][cc + 0], &Wl[m][cc + 0]);
            split_store(f.y, &Wh[m][cc + 1], &Wl[m][cc + 1]);
            split_store(f.z, &Wh[m][cc + 2], &Wl[m][cc + 2]);
            split_store(f.w, &Wh[m][cc + 3], &Wl[m][cc + 3]);
        }
        #pragma unroll
        for (int i = 0; i < 4; ++i) {           // keys tile 32x256 fp32
            int idx = i * 512 + t;
            int k = idx >> 6, cc = (idx & 63) * 4;
            float4 f = *(const float4*)(keys + ((size_t)b * TKn + kb + kt + k) * Hn + cc);
            split_store(f.x, &Kh[k][cc + 0], &Kl[k][cc + 0]);
            split_store(f.y, &Kh[k][cc + 1], &Kl[k][cc + 1]);
            split_store(f.z, &Kh[k][cc + 2], &Kl[k][cc + 2]);
            split_store(f.w, &Kh[k][cc + 3], &Kl[k][cc + 3]);
        }
        __syncthreads();

        #pragma unroll
        for (int ks = 0; ks < 2; ++ks) {
            const int kk = ks * 16;
            uint32_t ah[2][4], alr[2][4];
            #pragma unroll
            for (int i = 0; i < 2; ++i) {
                ldsmx4(ah[i],  sptr(&Wh[arow + i * 16][kk + acol]));
                ldsmx4(alr[i], sptr(&Wl[arow + i * 16][kk + acol]));
            }
            uint32_t bh[4][2], blr[4][2];
            #pragma unroll
            for (int j = 0; j < 4; ++j) {
                int h0 = wn * 32 + j * 8;
                ldsmx2t(bh[j],  sptr(&Kh[kk + krow][h0]));
                ldsmx2t(blr[j], sptr(&Kl[kk + krow][h0]));
            }
            #pragma unroll
            for (int i = 0; i < 2; ++i)
                #pragma unroll
                for (int j = 0; j < 4; ++j) {
                    mma16816(c[i][j], ah[i],  bh[j]);
                    mma16816(c[i][j], ah[i],  blr[j]);
                    mma16816(c[i][j], alr[i], bh[j]);
                }
        }
        __syncthreads();
    }

    #pragma unroll
    for (int i = 0; i < 2; ++i) {
        int row = wm * 32 + i * 16 + (lane >> 2);
        #pragma unroll
        for (int j = 0; j < 4; ++j) {
            int col = wn * 32 + j * 8 + (lane & 3) * 2;
            float* o = ctx + ((size_t)b * TQn + row) * Hn + col;
            atomicAdd(o,             c[i][j][0]);
            atomicAdd(o + 1,         c[i][j][1]);
            atomicAdd(o + 8 * Hn,     c[i][j][2]);
            atomicAdd(o + 8 * Hn + 1, c[i][j][3]);
        }
    }
}

// ---------------------------------------------------------------------------
// Launch. Inputs: query, keys, Wa_w, Wa_b (bias unused: cancels under softmax).
// Output: context [B*TQ*H f32] then weights [B*TQ*TK f32] (weights region is
// also the scores scratch before in-place softmax).
// ---------------------------------------------------------------------------
extern "C" void kernel_launch(void* const* d_in, const int* in_sizes, int n_in,
                              void* d_out, int out_size) {
    const float* query = (const float*)d_in[0];
    const float* keys  = (const float*)d_in[1];
    const float* W     = (const float*)d_in[2];

    float* ctx = (float*)d_out;
    float* wts = ctx + (size_t)Bn * TQn * Hn;

    k_transform<<<(Bn * TQn) / 8, 256>>>(query, W);
    k_scores<<<dim3(TKn / 128, Bn), 256>>>(keys, wts);
    k_softmax<<<Bn * TQn, 512>>>(wts);
    cudaMemsetAsync(ctx, 0, (size_t)Bn * TQn * Hn * sizeof(float), 0);
    k_context<<<dim3(TKn / 256, Bn), 512>>>(keys, wts, ctx);
}

// round 3
// speedup vs baseline: 1.5312x; 1.1084x over previous
#include <cuda_runtime.h>
#include <cuda_bf16.h>
#include <math.h>
#include <stdint.h>

#define Bn  8
#define TQn 64
#define TKn 8192
#define Hn  256

// Persistent bf16 hi/lo operands (split precision: x = hi + lo, err ~2^-24)
__device__ __nv_bfloat16 g_khi[Bn * TKn * Hn];
__device__ __nv_bfloat16 g_klo[Bn * TKn * Hn];
__device__ __nv_bfloat16 g_qhi[Bn * TQn * Hn];
__device__ __nv_bfloat16 g_qlo[Bn * TQn * Hn];
__device__ __nv_bfloat16 g_whi[Bn * TQn * TKn];
__device__ __nv_bfloat16 g_wlo[Bn * TQn * TKn];

// ---------------------------------------------------------------------------
// PTX helpers
// ---------------------------------------------------------------------------
__device__ __forceinline__ uint32_t sptr(const void* p) {
    return (uint32_t)__cvta_generic_to_shared(p);
}
__device__ __forceinline__ void cpasync16(uint32_t dst, const void* src) {
    asm volatile("cp.async.cg.shared.global [%0], [%1], 16;" :: "r"(dst), "l"(src));
}
__device__ __forceinline__ void cp_commit() {
    asm volatile("cp.async.commit_group;");
}
template <int N> __device__ __forceinline__ void cp_wait() {
    asm volatile("cp.async.wait_group %0;" :: "n"(N));
}
__device__ __forceinline__ void ldsmx4(uint32_t* r, uint32_t a) {
    asm volatile("ldmatrix.sync.aligned.m8n8.x4.shared.b16 {%0,%1,%2,%3},[%4];"
        : "=r"(r[0]), "=r"(r[1]), "=r"(r[2]), "=r"(r[3]) : "r"(a));
}
__device__ __forceinline__ void ldsmx2(uint32_t* r, uint32_t a) {
    asm volatile("ldmatrix.sync.aligned.m8n8.x2.shared.b16 {%0,%1},[%2];"
        : "=r"(r[0]), "=r"(r[1]) : "r"(a));
}
__device__ __forceinline__ void ldsmx2t(uint32_t* r, uint32_t a) {
    asm volatile("ldmatrix.sync.aligned.m8n8.x2.trans.shared.b16 {%0,%1},[%2];"
        : "=r"(r[0]), "=r"(r[1]) : "r"(a));
}
__device__ __forceinline__ void mma16816(float* c, const uint32_t* a, const uint32_t* b) {
    asm volatile(
        "mma.sync.aligned.m16n8k16.row.col.f32.bf16.bf16.f32 "
        "{%0,%1,%2,%3},{%4,%5,%6,%7},{%8,%9},{%0,%1,%2,%3};"
        : "+f"(c[0]), "+f"(c[1]), "+f"(c[2]), "+f"(c[3])
        : "r"(a[0]), "r"(a[1]), "r"(a[2]), "r"(a[3]), "r"(b[0]), "r"(b[1]));
}
// swizzled smem byte offset: 128B rows (64 bf16), seg = 16B chunk index
__device__ __forceinline__ uint32_t sw128(int row, int seg) {
    return (uint32_t)(row * 128 + ((seg ^ (row & 7)) << 4));
}
// 512B rows (256 bf16)
__device__ __forceinline__ uint32_t sw512(int row, int seg) {
    return (uint32_t)(row * 512 + ((seg ^ (row & 7)) << 4));
}

// ---------------------------------------------------------------------------
// Kernel 0: keys fp32 -> bf16 hi/lo (streaming, memory-bound)
// ---------------------------------------------------------------------------
__global__ void __launch_bounds__(256) k_convert(const float* __restrict__ keys) {
    const size_t Ng = (size_t)Bn * TKn * Hn / 8;         // 8-elem groups
    const float4* src = (const float4*)keys;
    uint4* dhi = (uint4*)g_khi;
    uint4* dlo = (uint4*)g_klo;
    size_t stride = (size_t)gridDim.x * blockDim.x;
    for (size_t i = (size_t)blockIdx.x * blockDim.x + threadIdx.x; i < Ng; i += stride) {
        float4 a = src[2 * i], b = src[2 * i + 1];
        __nv_bfloat162 h0 = __float22bfloat162_rn(make_float2(a.x, a.y));
        __nv_bfloat162 h1 = __float22bfloat162_rn(make_float2(a.z, a.w));
        __nv_bfloat162 h2 = __float22bfloat162_rn(make_float2(b.x, b.y));
        __nv_bfloat162 h3 = __float22bfloat162_rn(make_float2(b.z, b.w));
        float2 f0 = __bfloat1622float2(h0), f1 = __bfloat1622float2(h1);
        float2 f2 = __bfloat1622float2(h2), f3 = __bfloat1622float2(h3);
        __nv_bfloat162 l0 = __float22bfloat162_rn(make_float2(a.x - f0.x, a.y - f0.y));
        __nv_bfloat162 l1 = __float22bfloat162_rn(make_float2(a.z - f1.x, a.w - f1.y));
        __nv_bfloat162 l2 = __float22bfloat162_rn(make_float2(b.x - f2.x, b.y - f2.y));
        __nv_bfloat162 l3 = __float22bfloat162_rn(make_float2(b.z - f3.x, b.w - f3.y));
        uint4 uh, ul;
        uh.x = *(uint32_t*)&h0; uh.y = *(uint32_t*)&h1; uh.z = *(uint32_t*)&h2; uh.w = *(uint32_t*)&h3;
        ul.x = *(uint32_t*)&l0; ul.y = *(uint32_t*)&l1; ul.z = *(uint32_t*)&l2; ul.w = *(uint32_t*)&l3;
        dhi[i] = uh; dlo[i] = ul;
    }
}

// ---------------------------------------------------------------------------
// Kernel 1: qt = Q @ W (bias dropped: softmax-invariant), emits bf16 hi/lo
// ---------------------------------------------------------------------------
__global__ void k_transform(const float* __restrict__ query,
                            const float* __restrict__ W) {
    __shared__ float qs[8][Hn];
    const int t  = threadIdx.x;
    const int r0 = blockIdx.x * 8;

    #pragma unroll
    for (int i = 0; i < 8; ++i) {
        int idx = i * 256 + t;
        qs[idx >> 8][idx & 255] = query[(size_t)r0 * Hn + idx];
    }
    __syncthreads();

    float acc[8] = {0.f, 0.f, 0.f, 0.f, 0.f, 0.f, 0.f, 0.f};
    #pragma unroll 4
    for (int o = 0; o < Hn; ++o) {
        float wv = W[o * Hn + t];
        #pragma unroll
        for (int r = 0; r < 8; ++r) acc[r] += qs[r][o] * wv;
    }
    #pragma unroll
    for (int r = 0; r < 8; ++r) {
        __nv_bfloat16 h = __float2bfloat16(acc[r]);
        g_qhi[(size_t)(r0 + r) * Hn + t] = h;
        g_qlo[(size_t)(r0 + r) * Hn + t] = __float2bfloat16(acc[r] - __bfloat162float(h));
    }
}

// ---------------------------------------------------------------------------
// Kernel 2: scores = qt @ keys^T. M=64, N=128, K=256 in 4 chunks of 64.
// 8 warps (2m x 4n), warp tile 32x32, 3-term hi/lo MMA, cp.async 2-stage.
// Dyn smem/stage 48KB: Ah(8K) Al(8K) Bh(16K) Bl(16K). 2 stages = 96KB.
// ---------------------------------------------------------------------------
#define SC_STAGE 49152
__global__ void __launch_bounds__(256, 2)
k_scores(float* __restrict__ scr) {
    extern __shared__ char smem[];
    const uint32_t sb = sptr(smem);

    const int b  = blockIdx.y;
    const int n0 = blockIdx.x * 128;
    const int t = threadIdx.x, wid = t >> 5, lane = t & 31;
    const int wm = wid >> 2, wn = wid & 3;

    const __nv_bfloat16* qh = g_qhi + (size_t)b * TQn * Hn;
    const __nv_bfloat16* ql = g_qlo + (size_t)b * TQn * Hn;
    const __nv_bfloat16* kh = g_khi + ((size_t)b * TKn + n0) * Hn;
    const __nv_bfloat16* kl = g_klo + ((size_t)b * TKn + n0) * Hn;

    auto load_stage = [&](int s, int k0) {
        uint32_t base = sb + s * SC_STAGE;
        #pragma unroll
        for (int i = 0; i < 2; ++i) {                       // A: 64 rows x 8 segs
            int idx = i * 256 + t;
            int r = idx >> 3, g = idx & 7;
            uint32_t d = base + sw128(r, g);
            const size_t so = (size_t)r * Hn + k0 + g * 8;
            cpasync16(d,         qh + so);
            cpasync16(d + 8192,  ql + so);
        }
        #pragma unroll
        for (int i = 0; i < 4; ++i) {                       // B: 128 rows x 8 segs
            int idx = i * 256 + t;
            int r = idx >> 3, g = idx & 7;
            uint32_t d = base + 16384 + sw128(r, g);
            const size_t so = (size_t)r * Hn + k0 + g * 8;
            cpasync16(d,          kh + so);
            cpasync16(d + 16384,  kl + so);
        }
    };

    float c[2][4][4];
    #pragma unroll
    for (int i = 0; i < 2; ++i)
        #pragma unroll
        for (int j = 0; j < 4; ++j)
            #pragma unroll
            for (int v = 0; v < 4; ++v) c[i][j][v] = 0.f;

    load_stage(0, 0);
    cp_commit();

    for (int cc = 0; cc < 4; ++cc) {
        if (cc < 3) { load_stage((cc + 1) & 1, 64 * (cc + 1)); cp_commit(); cp_wait<1>(); }
        else        { cp_wait<0>(); }
        __syncthreads();

        const uint32_t base = sb + (cc & 1) * SC_STAGE;
        #pragma unroll
        for (int ks = 0; ks < 4; ++ks) {
            const int segb = ks * 2;
            uint32_t ah[2][4], al_[2][4];
            #pragma unroll
            for (int i = 0; i < 2; ++i) {
                int row = wm * 32 + i * 16 + (lane & 15);
                uint32_t off = sw128(row, segb + (lane >> 4));
                ldsmx4(ah[i],  base + off);
                ldsmx4(al_[i], base + 8192 + off);
            }
            uint32_t bh[4][2], bl_[4][2];
            #pragma unroll
            for (int j = 0; j < 4; ++j) {
                int row = wn * 32 + j * 8 + (lane & 7);
                uint32_t off = sw128(row, segb + ((lane >> 3) & 1));
                ldsmx2(bh[j],  base + 16384 + off);
                ldsmx2(bl_[j], base + 32768 + off);
            }
            #pragma unroll
            for (int i = 0; i < 2; ++i)
                #pragma unroll
                for (int j = 0; j < 4; ++j) {
                    mma16816(c[i][j], ah[i],  bh[j]);
                    mma16816(c[i][j], ah[i],  bl_[j]);
                    mma16816(c[i][j], al_[i], bh[j]);
                }
        }
        __syncthreads();
    }

    #pragma unroll
    for (int i = 0; i < 2; ++i) {
        int row = wm * 32 + i * 16 + (lane >> 2);
        #pragma unroll
        for (int j = 0; j < 4; ++j) {
            int col = n0 + wn * 32 + j * 8 + (lane & 3) * 2;
            float* o = scr + ((size_t)b * TQn + row) * TKn + col;
            *(float2*)o             = make_float2(c[i][j][0], c[i][j][1]);
            *(float2*)(o + 8 * TKn) = make_float2(c[i][j][2], c[i][j][3]);
        }
    }
}

// ---------------------------------------------------------------------------
// Kernel 3: row softmax over TK=8192; writes fp32 weights + bf16 hi/lo copies
// ---------------------------------------------------------------------------
__global__ void __launch_bounds__(512) k_softmax(float* __restrict__ w) {
    __shared__ float buf[TKn];
    __shared__ float red[16];

    const size_t row = blockIdx.x;
    float4* row4 = (float4*)(w + row * TKn);
    uint2* whi = (uint2*)(g_whi + row * TKn);
    uint2* wlo = (uint2*)(g_wlo + row * TKn);
    float4* b4 = (float4*)buf;
    const int t = threadIdx.x;

    float m = -3.4e38f;
    #pragma unroll
    for (int i = 0; i < 4; ++i) {
        float4 v = row4[i * 512 + t];
        b4[i * 512 + t] = v;
        m = fmaxf(m, fmaxf(fmaxf(v.x, v.y), fmaxf(v.z, v.w)));
    }
    #pragma unroll
    for (int o = 16; o; o >>= 1) m = fmaxf(m, __shfl_xor_sync(0xffffffffu, m, o));
    if ((t & 31) == 0) red[t >> 5] = m;
    __syncthreads();
    m = red[0];
    #pragma unroll
    for (int r = 1; r < 16; ++r) m = fmaxf(m, red[r]);

    float s = 0.f;
    #pragma unroll
    for (int i = 0; i < 4; ++i) {
        float4 v = b4[i * 512 + t];
        v.x = __expf(v.x - m); v.y = __expf(v.y - m);
        v.z = __expf(v.z - m); v.w = __expf(v.w - m);
        b4[i * 512 + t] = v;
        s += (v.x + v.y) + (v.z + v.w);
    }
    #pragma unroll
    for (int o = 16; o; o >>= 1) s += __shfl_xor_sync(0xffffffffu, s, o);
    __syncthreads();
    if ((t & 31) == 0) red[t >> 5] = s;
    __syncthreads();
    s = 0.f;
    #pragma unroll
    for (int r = 0; r < 16; ++r) s += red[r];
    const float inv = 1.f / s;

    #pragma unroll
    for (int i = 0; i < 4; ++i) {
        float4 v = b4[i * 512 + t];
        v.x *= inv; v.y *= inv; v.z *= inv; v.w *= inv;
        row4[i * 512 + t] = v;

        __nv_bfloat162 h01 = __float22bfloat162_rn(make_float2(v.x, v.y));
        __nv_bfloat162 h23 = __float22bfloat162_rn(make_float2(v.z, v.w));
        float2 f01 = __bfloat1622float2(h01), f23 = __bfloat1622float2(h23);
        __nv_bfloat162 l01 = __float22bfloat162_rn(make_float2(v.x - f01.x, v.y - f01.y));
        __nv_bfloat162 l23 = __float22bfloat162_rn(make_float2(v.z - f23.x, v.w - f23.y));
        uint2 uh, ul;
        uh.x = *(uint32_t*)&h01; uh.y = *(uint32_t*)&h23;
        ul.x = *(uint32_t*)&l01; ul.y = *(uint32_t*)&l23;
        whi[i * 512 + t] = uh;
        wlo[i * 512 + t] = ul;
    }
}

// ---------------------------------------------------------------------------
// Kernel 4: context += weights @ keys. 128 blocks (16/batch x 512 keys),
// M=64, N=256, k-chunk 64, 16 warps (2m x 8n), cp.async 2-stage.
// Dyn smem/stage 80KB: Wh(8K) Wl(8K) Kh(32K) Kl(32K). 2 stages = 160KB.
// ---------------------------------------------------------------------------
#define CX_STAGE 81920
__global__ void __launch_bounds__(512)
k_context(float* __restrict__ ctx) {
    extern __shared__ char smem[];
    const uint32_t sb = sptr(smem);

    const int b  = blockIdx.y;
    const int kb = blockIdx.x * 512;
    const int t = threadIdx.x, wid = t >> 5, lane = t & 31;
    const int wm = wid >> 3, wn = wid & 7;

    const __nv_bfloat16* wh = g_whi + (size_t)b * TQn * TKn;
    const __nv_bfloat16* wl = g_wlo + (size_t)b * TQn * TKn;
    const __nv_bfloat16* kh = g_khi + (size_t)b * TKn * Hn;
    const __nv_bfloat16* kl = g_klo + (size_t)b * TKn * Hn;

    auto load_stage = [&](int s, int kt) {
        uint32_t base = sb + s * CX_STAGE;
        {                                                   // W: 64 rows x 8 segs
            int r = t >> 3, g = t & 7;
            uint32_t d = base + sw128(r, g);
            const size_t so = (size_t)r * TKn + kb + kt + g * 8;
            cpasync16(d,        wh + so);
            cpasync16(d + 8192, wl + so);
        }
        #pragma unroll
        for (int i = 0; i < 4; ++i) {                       // K: 64 rows x 32 segs
            int idx = i * 512 + t;
            int r = idx >> 5, g = idx & 31;
            uint32_t d = base + 16384 + sw512(r, g);
            const size_t so = (size_t)(kb + kt + r) * Hn + g * 8;
            cpasync16(d,          kh + so);
            cpasync16(d + 32768,  kl + so);
        }
    };

    float c[2][4][4];
    #pragma unroll
    for (int i = 0; i < 2; ++i)
        #pragma unroll
        for (int j = 0; j < 4; ++j)
            #pragma unroll
            for (int v = 0; v < 4; ++v) c[i][j][v] = 0.f;

    load_stage(0, 0);
    cp_commit();

    for (int cc = 0; cc < 8; ++cc) {
        if (cc < 7) { load_stage((cc + 1) & 1, 64 * (cc + 1)); cp_commit(); cp_wait<1>(); }
        else        { cp_wait<0>(); }
        __syncthreads();

        const uint32_t base = sb + (cc & 1) * CX_STAGE;
        #pragma unroll
        for (int ks = 0; ks < 4; ++ks) {
            const int kk = ks * 16, segb = ks * 2;
            uint32_t ah[2][4], al_[2][4];
            #pragma unroll
            for (int i = 0; i < 2; ++i) {
                int row = wm * 32 + i * 16 + (lane & 15);
                uint32_t off = sw128(row, segb + (lane >> 4));
                ldsmx4(ah[i],  base + off);
                ldsmx4(al_[i], base + 8192 + off);
            }
            uint32_t bh[4][2], bl_[4][2];
            int krow = kk + (lane & 15);
            #pragma unroll
            for (int j = 0; j < 4; ++j) {
                uint32_t off = sw512(krow, wn * 4 + j);
                ldsmx2t(bh[j],  base + 16384 + off);
                ldsmx2t(bl_[j], base + 49152 + off);
            }
            #pragma unroll
            for (int i = 0; i < 2; ++i)
                #pragma unroll
                for (int j = 0; j < 4; ++j) {
                    mma16816(c[i][j], ah[i],  bh[j]);
                    mma16816(c[i][j], ah[i],  bl_[j]);
                    mma16816(c[i][j], al_[i], bh[j]);
                }
        }
        __syncthreads();
    }

    #pragma unroll
    for (int i = 0; i < 2; ++i) {
        int row = wm * 32 + i * 16 + (lane >> 2);
        #pragma unroll
        for (int j = 0; j < 4; ++j) {
            int col = wn * 32 + j * 8 + (lane & 3) * 2;
            float* o = ctx + ((size_t)b * TQn + row) * Hn + col;
            atomicAdd(o,              c[i][j][0]);
            atomicAdd(o + 1,          c[i][j][1]);
            atomicAdd(o + 8 * Hn,     c[i][j][2]);
            atomicAdd(o + 8 * Hn + 1, c[i][j][3]);
        }
    }
}

// ---------------------------------------------------------------------------
// Launch. Inputs: query, keys, Wa_w, Wa_b (bias cancels under softmax).
// Output: context [B*TQ*H f32] then weights [B*TQ*TK f32].
// ---------------------------------------------------------------------------
extern "C" void kernel_launch(void* const* d_in, const int* in_sizes, int n_in,
                              void* d_out, int out_size) {
    const float* query = (const float*)d_in[0];
    const float* keys  = (const float*)d_in[1];
    const float* W     = (const float*)d_in[2];

    float* ctx = (float*)d_out;
    float* wts = ctx + (size_t)Bn * TQn * Hn;

    cudaFuncSetAttribute(k_scores,  cudaFuncAttributeMaxDynamicSharedMemorySize, 2 * SC_STAGE);
    cudaFuncSetAttribute(k_context, cudaFuncAttributeMaxDynamicSharedMemorySize, 2 * CX_STAGE);

    k_convert<<<2048, 256>>>(keys);
    k_transform<<<(Bn * TQn) / 8, 256>>>(query, W);
    k_scores<<<dim3(TKn / 128, Bn), 256, 2 * SC_STAGE>>>(wts);
    k_softmax<<<Bn * TQn, 512>>>(wts);
    cudaMemsetAsync(ctx, 0, (size_t)Bn * TQn * Hn * sizeof(float), 0);
    k_context<<<dim3(TKn / 512, Bn), 512, 2 * CX_STAGE>>>(ctx);
}

// round 4
// speedup vs baseline: 1.7622x; 1.1508x over previous
#include <cuda_runtime.h>
#include <cuda_bf16.h>
#include <math.h>
#include <stdint.h>

#define Bn  8
#define TQn 64
#define TKn 8192
#define Hn  256

// qt = query @ W, stored pre-split as bf16 hi/lo (tiny: 512 KB)
__device__ __nv_bfloat16 g_qhi[Bn * TQn * Hn];
__device__ __nv_bfloat16 g_qlo[Bn * TQn * Hn];

// ---------------------------------------------------------------------------
// PTX helpers
// ---------------------------------------------------------------------------
__device__ __forceinline__ uint32_t sptr(const void* p) {
    return (uint32_t)__cvta_generic_to_shared(p);
}
__device__ __forceinline__ void cpasync16(uint32_t dst, const void* src) {
    asm volatile("cp.async.cg.shared.global [%0], [%1], 16;" :: "r"(dst), "l"(src));
}
__device__ __forceinline__ void cp_commit() { asm volatile("cp.async.commit_group;"); }
template <int N> __device__ __forceinline__ void cp_wait() {
    asm volatile("cp.async.wait_group %0;" :: "n"(N));
}
__device__ __forceinline__ void ldsmx4(uint32_t* r, uint32_t a) {
    asm volatile("ldmatrix.sync.aligned.m8n8.x4.shared.b16 {%0,%1,%2,%3},[%4];"
        : "=r"(r[0]), "=r"(r[1]), "=r"(r[2]), "=r"(r[3]) : "r"(a));
}
__device__ __forceinline__ void ldsmx2(uint32_t* r, uint32_t a) {
    asm volatile("ldmatrix.sync.aligned.m8n8.x2.shared.b16 {%0,%1},[%2];"
        : "=r"(r[0]), "=r"(r[1]) : "r"(a));
}
__device__ __forceinline__ void ldsmx2t(uint32_t* r, uint32_t a) {
    asm volatile("ldmatrix.sync.aligned.m8n8.x2.trans.shared.b16 {%0,%1},[%2];"
        : "=r"(r[0]), "=r"(r[1]) : "r"(a));
}
__device__ __forceinline__ void mma16816(float* c, const uint32_t* a, const uint32_t* b) {
    asm volatile(
        "mma.sync.aligned.m16n8k16.row.col.f32.bf16.bf16.f32 "
        "{%0,%1,%2,%3},{%4,%5,%6,%7},{%8,%9},{%0,%1,%2,%3};"
        : "+f"(c[0]), "+f"(c[1]), "+f"(c[2]), "+f"(c[3])
        : "r"(a[0]), "r"(a[1]), "r"(a[2]), "r"(a[3]), "r"(b[0]), "r"(b[1]));
}
// swizzled smem byte offsets (16B segments XOR'd by row)
__device__ __forceinline__ uint32_t sw128(int row, int seg) {
    return (uint32_t)(row * 128 + ((seg ^ (row & 7)) << 4));
}
__device__ __forceinline__ uint32_t sw512(int row, int seg) {
    return (uint32_t)(row * 512 + ((seg ^ (row & 7)) << 4));
}
// fp32x4 -> bf16 hi uint2 + lo uint2
__device__ __forceinline__ void split4(float4 f, uint2& uh, uint2& ul) {
    __nv_bfloat162 a = __float22bfloat162_rn(make_float2(f.x, f.y));
    __nv_bfloat162 b = __float22bfloat162_rn(make_float2(f.z, f.w));
    float2 fa = __bfloat1622float2(a), fb = __bfloat1622float2(b);
    __nv_bfloat162 la = __float22bfloat162_rn(make_float2(f.x - fa.x, f.y - fa.y));
    __nv_bfloat162 lb = __float22bfloat162_rn(make_float2(f.z - fb.x, f.w - fb.y));
    uh.x = *(uint32_t*)&a;  uh.y = *(uint32_t*)&b;
    ul.x = *(uint32_t*)&la; ul.y = *(uint32_t*)&lb;
}

// ---------------------------------------------------------------------------
// Kernel 1: qt = Q @ W (bias dropped: constant per softmax row) -> bf16 hi/lo
// ---------------------------------------------------------------------------
__global__ void k_transform(const float* __restrict__ query,
                            const float* __restrict__ W) {
    __shared__ float qs[8][Hn];
    const int t  = threadIdx.x;
    const int r0 = blockIdx.x * 8;

    #pragma unroll
    for (int i = 0; i < 8; ++i) {
        int idx = i * 256 + t;
        qs[idx >> 8][idx & 255] = query[(size_t)r0 * Hn + idx];
    }
    __syncthreads();

    float acc[8] = {0.f, 0.f, 0.f, 0.f, 0.f, 0.f, 0.f, 0.f};
    #pragma unroll 4
    for (int o = 0; o < Hn; ++o) {
        float wv = W[o * Hn + t];
        #pragma unroll
        for (int r = 0; r < 8; ++r) acc[r] += qs[r][o] * wv;
    }
    #pragma unroll
    for (int r = 0; r < 8; ++r) {
        __nv_bfloat16 h = __float2bfloat16(acc[r]);
        g_qhi[(size_t)(r0 + r) * Hn + t] = h;
        g_qlo[(size_t)(r0 + r) * Hn + t] = __float2bfloat16(acc[r] - __bfloat162float(h));
    }
}

// ---------------------------------------------------------------------------
// Kernel 2: scores = qt @ keys^T. M=64, N=128, K=256 (4 chunks of 64).
// 8 warps (2m x 4n). A (qt bf16) via cp.async 2-stage; keys fp32 via
// LDG->registers->split->STS (reg double buffer). 3-term hi/lo MMA.
// Stage: Ah 8K | Al 8K | Kh 16K | Kl 16K = 48K; x2 = 96KB.
// ---------------------------------------------------------------------------
#define SC_STAGE 49152
__global__ void __launch_bounds__(256, 2)
k_scores(const float* __restrict__ keys, float* __restrict__ scr) {
    extern __shared__ char smem[];
    const uint32_t sb = sptr(smem);

    const int b  = blockIdx.y;
    const int n0 = blockIdx.x * 128;
    const int t = threadIdx.x, wid = t >> 5, lane = t & 31;
    const int wm = wid >> 2, wn = wid & 3;

    const __nv_bfloat16* qh = g_qhi + (size_t)b * TQn * Hn;
    const __nv_bfloat16* ql = g_qlo + (size_t)b * TQn * Hn;
    const float* kg = keys + ((size_t)b * TKn + n0) * Hn;

    float4 kr[8];
    auto ldgK = [&](int cc) {
        const int k0 = cc * 64;
        #pragma unroll
        for (int i = 0; i < 8; ++i) {
            int idx = i * 256 + t, r = idx >> 4, c4 = idx & 15;
            kr[i] = *(const float4*)(kg + (size_t)r * Hn + k0 + c4 * 4);
        }
    };
    auto stsK = [&](int s) {
        char* base = smem + s * SC_STAGE + 16384;
        #pragma unroll
        for (int i = 0; i < 8; ++i) {
            int idx = i * 256 + t, r = idx >> 4, c4 = idx & 15;
            uint2 uh, ul;
            split4(kr[i], uh, ul);
            uint32_t off = sw128(r, c4 >> 1) + (c4 & 1) * 8;
            *(uint2*)(base + off)         = uh;
            *(uint2*)(base + 16384 + off) = ul;
        }
    };
    auto cpA = [&](int s, int cc) {
        const int k0 = cc * 64;
        #pragma unroll
        for (int i = 0; i < 2; ++i) {
            int idx = i * 256 + t, r = idx >> 3, g = idx & 7;
            uint32_t d = sb + s * SC_STAGE + sw128(r, g);
            const size_t so = (size_t)r * Hn + k0 + g * 8;
            cpasync16(d,        qh + so);
            cpasync16(d + 8192, ql + so);
        }
        cp_commit();
    };

    float c[2][4][4];
    #pragma unroll
    for (int i = 0; i < 2; ++i)
        #pragma unroll
        for (int j = 0; j < 4; ++j)
            #pragma unroll
            for (int v = 0; v < 4; ++v) c[i][j][v] = 0.f;

    // prologue
    ldgK(0); cpA(0, 0);
    stsK(0);
    ldgK(1); cpA(1, 1);
    cp_wait<1>(); __syncthreads();

    for (int cc = 0; cc < 4; ++cc) {
        const uint32_t base = sb + (cc & 1) * SC_STAGE;
        #pragma unroll
        for (int ks = 0; ks < 4; ++ks) {
            const int segb = ks * 2;
            uint32_t ah[2][4], al_[2][4];
            #pragma unroll
            for (int i = 0; i < 2; ++i) {
                int row = wm * 32 + i * 16 + (lane & 15);
                uint32_t off = sw128(row, segb + (lane >> 4));
                ldsmx4(ah[i],  base + off);
                ldsmx4(al_[i], base + 8192 + off);
            }
            uint32_t bh[4][2], bl_[4][2];
            #pragma unroll
            for (int j = 0; j < 4; ++j) {
                int row = wn * 32 + j * 8 + (lane & 7);
                uint32_t off = sw128(row, segb + ((lane >> 3) & 1));
                ldsmx2(bh[j],  base + 16384 + off);
                ldsmx2(bl_[j], base + 32768 + off);
            }
            #pragma unroll
            for (int i = 0; i < 2; ++i)
                #pragma unroll
                for (int j = 0; j < 4; ++j) {
                    mma16816(c[i][j], ah[i],  bh[j]);
                    mma16816(c[i][j], ah[i],  bl_[j]);
                    mma16816(c[i][j], al_[i], bh[j]);
                }
        }
        if (cc < 3) {
            __syncthreads();
            stsK((cc + 1) & 1);                 // regs hold chunk cc+1
            if (cc < 2) { ldgK(cc + 2); cpA(cc & 1, cc + 2); cp_wait<1>(); }
            else        { cp_wait<0>(); }
            __syncthreads();
        }
    }

    #pragma unroll
    for (int i = 0; i < 2; ++i) {
        int row = wm * 32 + i * 16 + (lane >> 2);
        #pragma unroll
        for (int j = 0; j < 4; ++j) {
            int col = n0 + wn * 32 + j * 8 + (lane & 3) * 2;
            float* o = scr + ((size_t)b * TQn + row) * TKn + col;
            *(float2*)o             = make_float2(c[i][j][0], c[i][j][1]);
            *(float2*)(o + 8 * TKn) = make_float2(c[i][j][2], c[i][j][3]);
        }
    }
}

// ---------------------------------------------------------------------------
// Kernel 3: in-place row softmax over TK=8192 (pure fp32, 32 MB pass)
// ---------------------------------------------------------------------------
__global__ void __launch_bounds__(512) k_softmax(float* __restrict__ w) {
    __shared__ float buf[TKn];
    __shared__ float red[16];

    float4* row4 = (float4*)(w + (size_t)blockIdx.x * TKn);
    float4* b4   = (float4*)buf;
    const int t = threadIdx.x;

    float m = -3.4e38f;
    #pragma unroll
    for (int i = 0; i < 4; ++i) {
        float4 v = row4[i * 512 + t];
        b4[i * 512 + t] = v;
        m = fmaxf(m, fmaxf(fmaxf(v.x, v.y), fmaxf(v.z, v.w)));
    }
    #pragma unroll
    for (int o = 16; o; o >>= 1) m = fmaxf(m, __shfl_xor_sync(0xffffffffu, m, o));
    if ((t & 31) == 0) red[t >> 5] = m;
    __syncthreads();
    m = red[0];
    #pragma unroll
    for (int r = 1; r < 16; ++r) m = fmaxf(m, red[r]);

    float s = 0.f;
    #pragma unroll
    for (int i = 0; i < 4; ++i) {
        float4 v = b4[i * 512 + t];
        v.x = __expf(v.x - m); v.y = __expf(v.y - m);
        v.z = __expf(v.z - m); v.w = __expf(v.w - m);
        b4[i * 512 + t] = v;
        s += (v.x + v.y) + (v.z + v.w);
    }
    #pragma unroll
    for (int o = 16; o; o >>= 1) s += __shfl_xor_sync(0xffffffffu, s, o);
    __syncthreads();
    if ((t & 31) == 0) red[t >> 5] = s;
    __syncthreads();
    s = 0.f;
    #pragma unroll
    for (int r = 0; r < 16; ++r) s += red[r];
    const float inv = 1.f / s;

    #pragma unroll
    for (int i = 0; i < 4; ++i) {
        float4 v = b4[i * 512 + t];
        v.x *= inv; v.y *= inv; v.z *= inv; v.w *= inv;
        row4[i * 512 + t] = v;
    }
}

// ---------------------------------------------------------------------------
// Kernel 4: context += weights @ keys. 16 blocks/batch x 512 keys each.
// M=64, N=256, k-chunk 64 (8 iters), 16 warps (2m x 8n). Both operands
// fp32 via LDG->split->STS (reg double buffer). atomicAdd epilogue.
// Stage: Wh 8K | Wl 8K | Kh 32K | Kl 32K = 80K; x2 = 160KB.
// ---------------------------------------------------------------------------
#define CX_STAGE 81920
__global__ void __launch_bounds__(512, 1)
k_context(const float* __restrict__ keys, const float* __restrict__ wts,
          float* __restrict__ ctx) {
    extern __shared__ char smem[];
    const uint32_t sb = sptr(smem);

    const int b  = blockIdx.y;
    const int kb = blockIdx.x * 512;
    const int t = threadIdx.x, wid = t >> 5, lane = t & 31;
    const int wm = wid >> 3, wn = wid & 7;

    const float* wg = wts + (size_t)b * TQn * TKn + kb;
    const float* kg = keys + ((size_t)b * TKn + kb) * Hn;

    float4 krr[8];  // keys tile 64x256: 8 float4/thread
    float4 wrr[2];  // weights tile 64x64: 2 float4/thread
    auto ldgT = [&](int cc) {
        const int kt = cc * 64;
        #pragma unroll
        for (int i = 0; i < 2; ++i) {
            int idx = i * 512 + t, r = idx >> 4, c4 = idx & 15;
            wrr[i] = *(const float4*)(wg + (size_t)r * TKn + kt + c4 * 4);
        }
        #pragma unroll
        for (int i = 0; i < 8; ++i) {
            int idx = i * 512 + t, r = idx >> 6, c4 = idx & 63;
            krr[i] = *(const float4*)(kg + (size_t)(kt + r) * Hn + c4 * 4);
        }
    };
    auto stsT = [&](int s) {
        char* base = smem + s * CX_STAGE;
        #pragma unroll
        for (int i = 0; i < 2; ++i) {
            int idx = i * 512 + t, r = idx >> 4, c4 = idx & 15;
            uint2 uh, ul;
            split4(wrr[i], uh, ul);
            uint32_t off = sw128(r, c4 >> 1) + (c4 & 1) * 8;
            *(uint2*)(base + off)        = uh;
            *(uint2*)(base + 8192 + off) = ul;
        }
        #pragma unroll
        for (int i = 0; i < 8; ++i) {
            int idx = i * 512 + t, r = idx >> 6, c4 = idx & 63;
            uint2 uh, ul;
            split4(krr[i], uh, ul);
            uint32_t off = sw512(r, c4 >> 1) + (c4 & 1) * 8;
            *(uint2*)(base + 16384 + off) = uh;
            *(uint2*)(base + 49152 + off) = ul;
        }
    };

    float c[2][4][4];
    #pragma unroll
    for (int i = 0; i < 2; ++i)
        #pragma unroll
        for (int j = 0; j < 4; ++j)
            #pragma unroll
            for (int v = 0; v < 4; ++v) c[i][j][v] = 0.f;

    // prologue
    ldgT(0);
    stsT(0);
    ldgT(1);
    __syncthreads();

    for (int cc = 0; cc < 8; ++cc) {
        const uint32_t base = sb + (cc & 1) * CX_STAGE;
        #pragma unroll
        for (int ks = 0; ks < 4; ++ks) {
            const int kk = ks * 16, segb = ks * 2;
            uint32_t ah[2][4], al_[2][4];
            #pragma unroll
            for (int i = 0; i < 2; ++i) {
                int row = wm * 32 + i * 16 + (lane & 15);
                uint32_t off = sw128(row, segb + (lane >> 4));
                ldsmx4(ah[i],  base + off);
                ldsmx4(al_[i], base + 8192 + off);
            }
            uint32_t bh[4][2], bl_[4][2];
            int krow = kk + (lane & 15);
            #pragma unroll
            for (int j = 0; j < 4; ++j) {
                uint32_t off = sw512(krow, wn * 4 + j);
                ldsmx2t(bh[j],  base + 16384 + off);
                ldsmx2t(bl_[j], base + 49152 + off);
            }
            #pragma unroll
            for (int i = 0; i < 2; ++i)
                #pragma unroll
                for (int j = 0; j < 4; ++j) {
                    mma16816(c[i][j], ah[i],  bh[j]);
                    mma16816(c[i][j], ah[i],  bl_[j]);
                    mma16816(c[i][j], al_[i], bh[j]);
                }
        }
        if (cc < 7) {
            __syncthreads();
            stsT((cc + 1) & 1);                 // regs hold chunk cc+1
            if (cc < 6) ldgT(cc + 2);
            __syncthreads();
        }
    }

    #pragma unroll
    for (int i = 0; i < 2; ++i) {
        int row = wm * 32 + i * 16 + (lane >> 2);
        #pragma unroll
        for (int j = 0; j < 4; ++j) {
            int col = wn * 32 + j * 8 + (lane & 3) * 2;
            float* o = ctx + ((size_t)b * TQn + row) * Hn + col;
            atomicAdd(o,              c[i][j][0]);
            atomicAdd(o + 1,          c[i][j][1]);
            atomicAdd(o + 8 * Hn,     c[i][j][2]);
            atomicAdd(o + 8 * Hn + 1, c[i][j][3]);
        }
    }
}

// ---------------------------------------------------------------------------
// Launch. Inputs: query, keys, Wa_w, Wa_b (bias cancels under softmax).
// Output: context [B*TQ*H f32] then weights [B*TQ*TK f32].
// ---------------------------------------------------------------------------
extern "C" void kernel_launch(void* const* d_in, const int* in_sizes, int n_in,
                              void* d_out, int out_size) {
    const float* query = (const float*)d_in[0];
    const float* keys  = (const float*)d_in[1];
    const float* W     = (const float*)d_in[2];

    float* ctx = (float*)d_out;
    float* wts = ctx + (size_t)Bn * TQn * Hn;

    cudaFuncSetAttribute(k_scores,  cudaFuncAttributeMaxDynamicSharedMemorySize, 2 * SC_STAGE);
    cudaFuncSetAttribute(k_context, cudaFuncAttributeMaxDynamicSharedMemorySize, 2 * CX_STAGE);

    k_transform<<<(Bn * TQn) / 8, 256>>>(query, W);
    k_scores<<<dim3(TKn / 128, Bn), 256, 2 * SC_STAGE>>>(keys, wts);
    k_softmax<<<Bn * TQn, 512>>>(wts);
    cudaMemsetAsync(ctx, 0, (size_t)Bn * TQn * Hn * sizeof(float), 0);
    k_context<<<dim3(TKn / 512, Bn), 512, 2 * CX_STAGE>>>(keys, wts, ctx);
}